// round 17
// baseline (speedup 1.0000x reference)
#include <cuda_runtime.h>
#include <math.h>

// Problem constants (fixed by the dataset)
#define D      300
#define D4     75      // D / 4 (float4 slabs; 1200B rows are 16B-aligned)
#define NCTX   10
#define NNEG   20
#define NROWS  21      // 1 positive + 20 negatives
#define B_MAX  16384
#define T2     224     // 7 warps x 3 concurrent rows = 21 exactly
#define NWARPS (T2 / 32)

// Scratch: per-batch mean-pooled context embedding (19.66 MB),
// double accumulator, and a ticket for the last-CTA finalize.
__device__ __align__(16) float g_ctx_mean[(size_t)B_MAX * D];
__device__ double g_acc;
__device__ unsigned int g_ticket;   // zero-init; reset by last CTA each launch

__device__ __forceinline__ float log_sigmoid(float x) {
    // numerically stable: min(x,0) - log1p(exp(-|x|))
    return fminf(x, 0.0f) - log1pf(__expf(-fabsf(x)));
}

__device__ __forceinline__ float dot4(float4 a, float4 c, float p) {
    p = fmaf(a.x, c.x, p);
    p = fmaf(a.y, c.y, p);
    p = fmaf(a.z, c.z, p);
    p = fmaf(a.w, c.w, p);
    return p;
}

// ---- Kernel 1: ctx mean. Only in_embed traffic -> best L2 behavior for it.
//      Block 0 also re-zeroes the accumulator (safe: K2 runs strictly after). ----
__global__ __launch_bounds__(96)
void ctx_mean_kernel(const int* __restrict__ ctx_words,  // [B, NCTX]
                     const float* __restrict__ in_w)     // [V, D]
{
    const int b   = blockIdx.x;
    const int tid = threadIdx.x;

    if (b == 0 && tid == 95) g_acc = 0.0;

    __shared__ int s_cidx[NCTX];
    if (tid < NCTX) s_cidx[tid] = ctx_words[b * NCTX + tid];
    __syncthreads();

    if (tid < D4) {
        float4 acc = make_float4(0.f, 0.f, 0.f, 0.f);
        #pragma unroll
        for (int c = 0; c < NCTX; c++) {
            const float4* row = reinterpret_cast<const float4*>(
                in_w + (size_t)s_cidx[c] * D);
            float4 v = __ldg(&row[tid]);
            acc.x += v.x; acc.y += v.y; acc.z += v.z; acc.w += v.w;
        }
        const float inv = 1.0f / (float)NCTX;
        float4* dst = reinterpret_cast<float4*>(g_ctx_mean + (size_t)b * D);
        // evict-first store: dead data for the rest of K1, keeps in_w in L2
        __stcs(&dst[tid],
               make_float4(acc.x * inv, acc.y * inv, acc.z * inv, acc.w * inv));
    }
}

// ---- Kernel 2: 21 dot products + log_sigmoid. Each warp owns 3 rows processed
//      CONCURRENTLY (up to 9 outstanding LDG.128 per thread) to hide DRAM latency.
//      Per-CTA double atomic; last CTA finalizes the scalar output. ----
__global__ __launch_bounds__(T2)
void score_kernel(const int* __restrict__ center_word, // [B]
                  const int* __restrict__ neg_words,   // [B, NNEG]
                  const float* __restrict__ out_w,     // [V, D]
                  float* __restrict__ out,             // [1]
                  float neg_inv_B)
{
    const int b    = blockIdx.x;
    const int tid  = threadIdx.x;
    const int warp = tid >> 5;
    const int lane = tid & 31;

    __shared__ __align__(16) float4 s_cm[D4];
    __shared__ float s_warp[NWARPS];
    __shared__ int   s_tidx[NROWS];

    // stage target indices (warp 0) and ctx-mean (streaming, evict-first)
    if (tid < NROWS)
        s_tidx[tid] = (tid == 0) ? center_word[b]
                                 : neg_words[b * NNEG + (tid - 1)];
    if (tid >= 64 && tid < 64 + D4) {
        int j = tid - 64;
        s_cm[j] = __ldcs(reinterpret_cast<const float4*>(
                             g_ctx_mean + (size_t)b * D) + j);
    }
    __syncthreads();

    // three rows per warp, interleaved for MLP
    const float4* row0 = reinterpret_cast<const float4*>(
        out_w + (size_t)s_tidx[warp] * D);
    const float4* row1 = reinterpret_cast<const float4*>(
        out_w + (size_t)s_tidx[warp + NWARPS] * D);
    const float4* row2 = reinterpret_cast<const float4*>(
        out_w + (size_t)s_tidx[warp + 2 * NWARPS] * D);

    const int j0 = lane, j1 = lane + 32, j2 = lane + 64;
    const bool has2 = (j2 < D4);   // lanes 0..10

    // issue ALL independent global loads first (up to 9 LDG.128 in flight)
    float4 a00 = __ldg(&row0[j0]);
    float4 a10 = __ldg(&row1[j0]);
    float4 a20 = __ldg(&row2[j0]);
    float4 a01 = __ldg(&row0[j1]);
    float4 a11 = __ldg(&row1[j1]);
    float4 a21 = __ldg(&row2[j1]);
    float4 a02, a12, a22;
    if (has2) {
        a02 = __ldg(&row0[j2]);
        a12 = __ldg(&row1[j2]);
        a22 = __ldg(&row2[j2]);
    }

    float4 c0 = s_cm[j0];
    float4 c1 = s_cm[j1];

    float p0 = 0.f, p1 = 0.f, p2 = 0.f;
    p0 = dot4(a00, c0, p0);  p1 = dot4(a10, c0, p1);  p2 = dot4(a20, c0, p2);
    p0 = dot4(a01, c1, p0);  p1 = dot4(a11, c1, p1);  p2 = dot4(a21, c1, p2);
    if (has2) {
        float4 c2 = s_cm[j2];
        p0 = dot4(a02, c2, p0);  p1 = dot4(a12, c2, p1);  p2 = dot4(a22, c2, p2);
    }

    #pragma unroll
    for (int o = 16; o > 0; o >>= 1) {
        p0 += __shfl_xor_sync(0xffffffffu, p0, o);
        p1 += __shfl_xor_sync(0xffffffffu, p1, o);
        p2 += __shfl_xor_sync(0xffffffffu, p2, o);
    }

    if (lane == 0) {
        // row indices: warp (pos iff warp==0), warp+7, warp+14 (always negatives)
        float wsum = log_sigmoid(warp == 0 ? p0 : -p0)
                   + log_sigmoid(-p1)
                   + log_sigmoid(-p2);
        s_warp[warp] = wsum;
    }
    __syncthreads();

    if (tid == 0) {
        float s = 0.0f;
        #pragma unroll
        for (int w = 0; w < NWARPS; w++) s += s_warp[w];
        atomicAdd(&g_acc, (double)s);            // order-independent accumulation
        __threadfence();
        unsigned t = atomicAdd(&g_ticket, 1u);
        if (t == gridDim.x - 1) {                // last CTA: finalize + reset
            g_ticket = 0;                        // deterministic across graph replays
            double total = atomicAdd(&g_acc, 0.0);  // L2-coherent read
            out[0] = (float)total * neg_inv_B;
        }
    }
}

extern "C" void kernel_launch(void* const* d_in, const int* in_sizes, int n_in,
                              void* d_out, int out_size) {
    const int*   ctx_words   = (const int*)d_in[0];   // [B, NCTX]
    const int*   center_word = (const int*)d_in[1];   // [B]
    const int*   neg_words   = (const int*)d_in[2];   // [B, NNEG]
    const float* in_w        = (const float*)d_in[3]; // [V, D]
    const float* out_w       = (const float*)d_in[4]; // [V, D]
    float*       out         = (float*)d_out;

    const int B = in_sizes[1];

    ctx_mean_kernel<<<B, 96>>>(ctx_words, in_w);
    score_kernel<<<B, T2>>>(center_word, neg_words, out_w, out,
                            -1.0f / (float)B);
}